// round 6
// baseline (speedup 1.0000x reference)
#include <cuda_runtime.h>

#define NN 8192
#define DD 256
#define KK 8
#define CC 1024
#define MARGIN2 0.7f

// persistent scratch (no allocations allowed)
__device__ __align__(16) float g_centersT[DD * CC];  // [d][c] transposed centers
__device__ float g_sq[CC];         // ||center||^2 per class
__device__ float g_pc[CC];         // per-class sum of dist_pc over its 8 samples
__device__ float g_anp[16 * CC];   // per-(b-tile, a-class) hinge partial sums

__device__ __forceinline__ float warpSum(float v) {
#pragma unroll
    for (int o = 16; o > 0; o >>= 1) v += __shfl_xor_sync(0xffffffffu, v, o);
    return v;
}

// ---------------------------------------------------------------------------
// k1: 4 classes per block (grid 256 x 256 threads, 8 warps).
// Warp w owns 4 rows; class j = w/2. dist_pc via 2 - 2*(x_hat . c_hat).
// Writes ONLY the transposed center layout (contiguous 16B+ chunks).
// ---------------------------------------------------------------------------
__global__ __launch_bounds__(256) void k1_center(const float* __restrict__ in) {
    int tid = threadIdx.x, lane = tid & 31, w = tid >> 5;
    int c0 = blockIdx.x * 4;

    __shared__ __align__(16) float pw[8][260];   // per-warp center partials
    __shared__ __align__(16) float cen[4][260];  // class centers
    __shared__ float ssq[4];
    __shared__ float pd[8];

    int R0 = c0 * KK + w * 4;                    // first of this warp's 4 rows
    const float4* in4 = (const float4*)in;
    float4 lo[4], hi[4];
#pragma unroll
    for (int r = 0; r < 4; r++) {
        lo[r] = in4[(size_t)(R0 + r) * 64 + lane];
        hi[r] = in4[(size_t)(R0 + r) * 64 + lane + 32];
    }
#pragma unroll
    for (int r = 0; r < 4; r++) {
        float ss = lo[r].x*lo[r].x + lo[r].y*lo[r].y + lo[r].z*lo[r].z + lo[r].w*lo[r].w
                 + hi[r].x*hi[r].x + hi[r].y*hi[r].y + hi[r].z*hi[r].z + hi[r].w*hi[r].w;
        ss = warpSum(ss);
        float rn = rsqrtf(ss);
        lo[r].x *= rn; lo[r].y *= rn; lo[r].z *= rn; lo[r].w *= rn;
        hi[r].x *= rn; hi[r].y *= rn; hi[r].z *= rn; hi[r].w *= rn;
    }
    // per-warp partial center (4 of the class's 8 rows)
    float4 pl = make_float4(0.f,0.f,0.f,0.f), ph = make_float4(0.f,0.f,0.f,0.f);
#pragma unroll
    for (int r = 0; r < 4; r++) {
        pl.x += lo[r].x; pl.y += lo[r].y; pl.z += lo[r].z; pl.w += lo[r].w;
        ph.x += hi[r].x; ph.y += hi[r].y; ph.z += hi[r].z; ph.w += hi[r].w;
    }
    *(float4*)&pw[w][lane * 4]       = pl;
    *(float4*)&pw[w][128 + lane * 4] = ph;
    __syncthreads();

    // combine warp pairs -> class center; write transposed global layout
#pragma unroll
    for (int e = 0; e < 4; e++) {
        int idx = tid + e * 256;       // 0..1023 over (d,j)
        int j = idx & 3, d = idx >> 2;
        float v = (pw[2 * j][d] + pw[2 * j + 1][d]) * 0.125f;
        cen[j][d] = v;
        g_centersT[d * CC + c0 + j] = v;
    }
    __syncthreads();

    if (w < 4) {   // warp w computes ||cen_w||^2
        float4 a = *(float4*)&cen[w][lane * 4];
        float4 b = *(float4*)&cen[w][128 + lane * 4];
        float s = a.x*a.x + a.y*a.y + a.z*a.z + a.w*a.w
                + b.x*b.x + b.y*b.y + b.z*b.z + b.w*b.w;
        s = warpSum(s);
        if (lane == 0) { g_sq[c0 + w] = s; ssq[w] = s; }
    }
    __syncthreads();

    // dist_pc: rows still in registers; dist = sqrt(2 - 2 * dot / ||c||)
    int j = w >> 1;
    float rq = rsqrtf(ssq[j]);
    float4 cl = *(float4*)&cen[j][lane * 4];
    float4 ch = *(float4*)&cen[j][128 + lane * 4];
    float ds = 0.f;
#pragma unroll
    for (int r = 0; r < 4; r++) {
        float dt = lo[r].x*cl.x + lo[r].y*cl.y + lo[r].z*cl.z + lo[r].w*cl.w
                 + hi[r].x*ch.x + hi[r].y*ch.y + hi[r].z*ch.z + hi[r].w*ch.w;
        dt = warpSum(dt);
        ds += sqrtf(fmaxf(2.f - 2.f * dt * rq, 0.f));
    }
    if (lane == 0) pd[w] = ds;
    __syncthreads();
    if (tid < 4) g_pc[c0 + tid] = pd[2 * tid] + pd[2 * tid + 1];
}

// ---------------------------------------------------------------------------
// k2: Gram + hinge. Tiled GEMM, 128(a) x 64(b) per block, BK=16, 8 chunks... 16 chunks.
// A tile stored DUPLICATED in smem so ld.shared.v2.b64 yields (a,a) f32x2 pairs.
// Inner product via fma.rn.f32x2 (2 MACs / issue slot). Double-buffered.
// grid = 8(a-tiles) * 16(b-tiles) = 128 blocks x 512 threads.
// ---------------------------------------------------------------------------
__device__ __forceinline__ void fma2(unsigned long long& d,
                                     unsigned long long a, unsigned long long b) {
    asm("fma.rn.f32x2 %0, %1, %2, %0;" : "+l"(d) : "l"(a), "l"(b));
}

__global__ __launch_bounds__(512) void k2_gram() {
    int tid = threadIdx.x;
    int tx = tid & 15, ty = tid >> 4;           // b-group, a-group
    int a0 = (blockIdx.x & 7) * 128;
    int tb = blockIdx.x >> 3;
    int b0 = tb * 64;

    __shared__ __align__(16) float Ad[2][16][264];  // duplicated A: [d][2r],[d][2r+1]=A[r][d]
    __shared__ __align__(16) float Bs[2][16][68];

    const int adB = tid >> 6;                   // 0..7 (A-stage d within half)
    const int akk = tid & 63;                   // A-stage column-pair index
    const int bd  = tid >> 4;                   // B-stage d (valid tid<256)
    const int bc4 = (tid & 15) << 2;

    // stage chunk 0
#pragma unroll
    for (int e = 0; e < 2; e++) {
        int d = adB + e * 8;
        float2 v = *(const float2*)&g_centersT[(size_t)d * CC + a0 + 2 * akk];
        *(float4*)&Ad[0][d][4 * akk] = make_float4(v.x, v.x, v.y, v.y);
    }
    if (tid < 256) {
        float4 v = *(const float4*)&g_centersT[(size_t)bd * CC + b0 + bc4];
        *(float4*)&Bs[0][bd][bc4] = v;
    }
    __syncthreads();

    unsigned long long c00=0,c01=0,c10=0,c11=0,c20=0,c21=0,c30=0,c31=0;

    unsigned aBase = (unsigned)__cvta_generic_to_shared(&Ad[0][0][0]) + (unsigned)(ty * 32);
    unsigned bBase = (unsigned)__cvta_generic_to_shared(&Bs[0][0][0]) + (unsigned)(tx * 16);
    const unsigned ABUF = 16 * 264 * 4;
    const unsigned BBUF = 16 * 68 * 4;

    int buf = 0;
    for (int ch = 0; ch < 16; ch++) {
        float2 pA0, pA1; float4 pB;
        if (ch < 15) {                           // prefetch next chunk into regs
            int dc = (ch + 1) * 16;
            pA0 = *(const float2*)&g_centersT[(size_t)(dc + adB)     * CC + a0 + 2 * akk];
            pA1 = *(const float2*)&g_centersT[(size_t)(dc + adB + 8) * CC + a0 + 2 * akk];
            if (tid < 256)
                pB = *(const float4*)&g_centersT[(size_t)(dc + bd) * CC + b0 + bc4];
        }
        unsigned ap = aBase + (unsigned)buf * ABUF;
        unsigned bp = bBase + (unsigned)buf * BBUF;
#pragma unroll
        for (int d = 0; d < 16; d++) {
            unsigned long long aa0, aa1, aa2, aa3, b01, b23;
            asm("ld.shared.v2.b64 {%0,%1}, [%2];" : "=l"(aa0), "=l"(aa1) : "r"(ap + d * 1056u));
            asm("ld.shared.v2.b64 {%0,%1}, [%2];" : "=l"(aa2), "=l"(aa3) : "r"(ap + d * 1056u + 16u));
            asm("ld.shared.v2.b64 {%0,%1}, [%2];" : "=l"(b01), "=l"(b23) : "r"(bp + d * 272u));
            fma2(c00, aa0, b01); fma2(c01, aa0, b23);
            fma2(c10, aa1, b01); fma2(c11, aa1, b23);
            fma2(c20, aa2, b01); fma2(c21, aa2, b23);
            fma2(c30, aa3, b01); fma2(c31, aa3, b23);
        }
        if (ch < 15) {
            int nb = buf ^ 1;
            *(float4*)&Ad[nb][adB][4 * akk]     = make_float4(pA0.x, pA0.x, pA0.y, pA0.y);
            *(float4*)&Ad[nb][adB + 8][4 * akk] = make_float4(pA1.x, pA1.x, pA1.y, pA1.y);
            if (tid < 256) *(float4*)&Bs[nb][bd][bc4] = pB;
            __syncthreads();
            buf = nb;
        }
    }

    // unpack dots
    float dots[4][4];
#define UNPK(u, l_, h_) asm("mov.b64 {%0,%1}, %2;" : "=f"(l_), "=f"(h_) : "l"(u))
    UNPK(c00, dots[0][0], dots[0][1]); UNPK(c01, dots[0][2], dots[0][3]);
    UNPK(c10, dots[1][0], dots[1][1]); UNPK(c11, dots[1][2], dots[1][3]);
    UNPK(c20, dots[2][0], dots[2][1]); UNPK(c21, dots[2][2], dots[2][3]);
    UNPK(c30, dots[3][0], dots[3][1]); UNPK(c31, dots[3][2], dots[3][3]);
#undef UNPK

    int ag = a0 + ty * 4, bg = b0 + tx * 4;
    float4 qa = *(const float4*)&g_sq[ag];
    float4 qb = *(const float4*)&g_sq[bg];
    float sqav[4] = {qa.x, qa.y, qa.z, qa.w};
    float sqbv[4] = {qb.x, qb.y, qb.z, qb.w};

#pragma unroll
    for (int i = 0; i < 4; i++) {
        float rs = 0.f;
#pragma unroll
        for (int jj = 0; jj < 4; jj++) {
            float v = sqav[i] + sqbv[jj] - 2.f * dots[i][jj];
            float dist = sqrtf(fmaxf(v, 1e-12f));
            float h = fmaxf(MARGIN2 - dist, 0.f);
            if (ag + i == bg + jj) h = 0.f;     // exclude same class
            rs += h;
        }
#pragma unroll
        for (int o = 1; o < 16; o <<= 1)
            rs += __shfl_xor_sync(0xffffffffu, rs, o, 16);
        if (tx == 0) g_anp[tb * CC + ag + i] = rs;  // deterministic, no atomics
    }
}

// ---------------------------------------------------------------------------
// k3: final reductions -> 3 scalars
// ---------------------------------------------------------------------------
__global__ __launch_bounds__(256) void k3_final(float* __restrict__ out, int out_size) {
    int t = threadIdx.x, lane = t & 31, w = t >> 5;
    float pcs = 0.f, ans = 0.f;
#pragma unroll
    for (int e = 0; e < 4; e++) pcs += g_pc[t + e * 256];
#pragma unroll
    for (int bt = 0; bt < 16; bt++)
#pragma unroll
        for (int e = 0; e < 4; e++) ans += g_anp[bt * CC + t + e * 256];
    pcs = warpSum(pcs);
    ans = warpSum(ans);
    __shared__ float rp[8], ra[8];
    if (lane == 0) { rp[w] = pcs; ra[w] = ans; }
    __syncthreads();
    if (t == 0) {
        float P = 0.f, A = 0.f;
#pragma unroll
        for (int i = 0; i < 8; i++) { P += rp[i]; A += ra[i]; }
        float pc_mean = P * (1.f / (float)NN);
        // dist_an[a] = KK * rowsum / (NN - KK); mean over CC anchors
        float an_mean = A * ((float)KK / ((float)(NN - KK) * (float)CC));
        if (out_size > 0) out[0] = pc_mean + an_mean;
        if (out_size > 1) out[1] = pc_mean;
        if (out_size > 2) out[2] = an_mean;
    }
    for (int i = t + 3; i < out_size; i += 256) out[i] = 0.f;
}

extern "C" void kernel_launch(void* const* d_in, const int* in_sizes, int n_in,
                              void* d_out, int out_size) {
    const float* in = (const float*)d_in[0];
    // targets (d_in[1]) are arange(N)//K by construction: contiguous K-blocks.
    k1_center<<<CC / 4, 256>>>(in);
    k2_gram<<<128, 512>>>();
    k3_final<<<1, 256>>>((float*)d_out, out_size);
}

// round 7
// speedup vs baseline: 1.5336x; 1.5336x over previous
#include <cuda_runtime.h>

#define NN 8192
#define DD 256
#define KK 8
#define CC 1024
#define MARGIN2 0.7f

// persistent scratch (no allocations allowed)
__device__ __align__(16) float g_centers[CC * DD];   // row-major class centers
__device__ float g_sq[CC];         // ||center||^2 per class
__device__ float g_pc[CC];         // per-class sum of dist_pc over its 8 samples
__device__ float g_anp[16 * CC];   // per-(b-tile, a-class) hinge partial sums

__device__ __forceinline__ float warpSum(float v) {
#pragma unroll
    for (int o = 16; o > 0; o >>= 1) v += __shfl_xor_sync(0xffffffffu, v, o);
    return v;
}

// ---------------------------------------------------------------------------
// k1: one block per class (R1 structure, minus the transposed-layout scatter).
// Warp w normalizes row c*8+w; block builds center, ||c||^2, dist_pc partial.
// ---------------------------------------------------------------------------
__global__ __launch_bounds__(256) void k1_center(const float* __restrict__ in) {
    int c = blockIdx.x;
    int t = threadIdx.x;
    int w = t >> 5, lane = t & 31;

    __shared__ __align__(16) float xs[KK][DD];   // normalized rows
    __shared__ __align__(16) float cen[DD];
    __shared__ float wred[KK];
    __shared__ float s_csq;

    const float4* row = (const float4*)(in + (size_t)(c * KK + w) * DD);
    float4 v0 = row[lane];
    float4 v1 = row[lane + 32];
    float ss = v0.x * v0.x + v0.y * v0.y + v0.z * v0.z + v0.w * v0.w
             + v1.x * v1.x + v1.y * v1.y + v1.z * v1.z + v1.w * v1.w;
    ss = warpSum(ss);
    float rn = rsqrtf(ss);
    v0.x *= rn; v0.y *= rn; v0.z *= rn; v0.w *= rn;
    v1.x *= rn; v1.y *= rn; v1.z *= rn; v1.w *= rn;
    ((float4*)xs[w])[lane] = v0;
    ((float4*)xs[w])[lane + 32] = v1;
    __syncthreads();

    // center over 8 rows at dim t; coalesced row-major store only
    float s = 0.f;
#pragma unroll
    for (int r = 0; r < KK; r++) s += xs[r][t];
    s *= (1.f / KK);
    cen[t] = s;
    g_centers[c * DD + t] = s;

    float p = warpSum(s * s);
    if (lane == 0) wred[w] = p;
    __syncthreads();
    if (t == 0) {
        float cs = 0.f;
#pragma unroll
        for (int r = 0; r < KK; r++) cs += wred[r];
        g_sq[c] = cs;
        s_csq = cs;
    }
    __syncthreads();
    float inv = rsqrtf(s_csq);

    // dist_pc for row w: ||x_hat - c_hat||
    const float4* c4 = (const float4*)cen;
    float4 c0 = c4[lane], c1 = c4[lane + 32];
    float acc = 0.f, dx;
    dx = v0.x - c0.x * inv; acc += dx * dx;
    dx = v0.y - c0.y * inv; acc += dx * dx;
    dx = v0.z - c0.z * inv; acc += dx * dx;
    dx = v0.w - c0.w * inv; acc += dx * dx;
    dx = v1.x - c1.x * inv; acc += dx * dx;
    dx = v1.y - c1.y * inv; acc += dx * dx;
    dx = v1.z - c1.z * inv; acc += dx * dx;
    dx = v1.w - c1.w * inv; acc += dx * dx;
    acc = warpSum(acc);
    if (lane == 0) wred[w] = sqrtf(acc);   // MARGIN1 = 0
    __syncthreads();
    if (t == 0) {
        float s2 = 0.f;
#pragma unroll
        for (int r = 0; r < KK; r++) s2 += wred[r];
        g_pc[c] = s2;
    }
}

// ---------------------------------------------------------------------------
// k2: Gram + hinge. Register-blocked tiled GEMM, both operands from row-major
// g_centers (transpose during smem staging). Block tile 128a x 64b, BK=16,
// per-thread 8a x 4b fp32 accumulators. grid = 8 * 16 = 128 blocks x 256 thr.
// Double-buffered smem, one __syncthreads per chunk.
// ---------------------------------------------------------------------------
#define AS_STRIDE 132
#define BS_STRIDE 68

__global__ __launch_bounds__(256) void k2_gram() {
    int tid = threadIdx.x;
    int tx = tid & 15, ty = tid >> 4;           // b-subtile (4 cols), a-subtile (8 rows)
    int a0 = (blockIdx.x & 7) * 128;
    int tb = blockIdx.x >> 3;
    int b0 = tb * 64;

    __shared__ __align__(16) float As[2][16][AS_STRIDE];  // [d][a-local]
    __shared__ __align__(16) float Bs[2][16][BS_STRIDE];  // [d][b-local]

    const int sr = tid >> 2;      // staging row (0..63)
    const int sf = tid & 3;       // staging float4 index within 16-d chunk

    const float* __restrict__ C = g_centers;

    // stage chunk 0
    {
        float4 va0 = *(const float4*)&C[(size_t)(a0 + sr)      * DD + sf * 4];
        float4 va1 = *(const float4*)&C[(size_t)(a0 + sr + 64) * DD + sf * 4];
        float4 vb  = *(const float4*)&C[(size_t)(b0 + sr)      * DD + sf * 4];
        As[0][sf * 4 + 0][sr]      = va0.x; As[0][sf * 4 + 1][sr]      = va0.y;
        As[0][sf * 4 + 2][sr]      = va0.z; As[0][sf * 4 + 3][sr]      = va0.w;
        As[0][sf * 4 + 0][sr + 64] = va1.x; As[0][sf * 4 + 1][sr + 64] = va1.y;
        As[0][sf * 4 + 2][sr + 64] = va1.z; As[0][sf * 4 + 3][sr + 64] = va1.w;
        Bs[0][sf * 4 + 0][sr] = vb.x; Bs[0][sf * 4 + 1][sr] = vb.y;
        Bs[0][sf * 4 + 2][sr] = vb.z; Bs[0][sf * 4 + 3][sr] = vb.w;
    }
    __syncthreads();

    float acc[8][4];
#pragma unroll
    for (int i = 0; i < 8; i++)
#pragma unroll
        for (int j = 0; j < 4; j++) acc[i][j] = 0.f;

    int buf = 0;
    for (int ch = 0; ch < 16; ch++) {
        float4 pa0, pa1, pb;
        if (ch < 15) {
            int dc = (ch + 1) * 16;
            pa0 = *(const float4*)&C[(size_t)(a0 + sr)      * DD + dc + sf * 4];
            pa1 = *(const float4*)&C[(size_t)(a0 + sr + 64) * DD + dc + sf * 4];
            pb  = *(const float4*)&C[(size_t)(b0 + sr)      * DD + dc + sf * 4];
        }
#pragma unroll
        for (int d = 0; d < 16; d++) {
            float4 a04 = *(const float4*)&As[buf][d][ty * 8];
            float4 a14 = *(const float4*)&As[buf][d][ty * 8 + 4];
            float4 b4  = *(const float4*)&Bs[buf][d][tx * 4];
            float av[8] = {a04.x, a04.y, a04.z, a04.w, a14.x, a14.y, a14.z, a14.w};
            float bv[4] = {b4.x, b4.y, b4.z, b4.w};
#pragma unroll
            for (int i = 0; i < 8; i++)
#pragma unroll
                for (int j = 0; j < 4; j++) acc[i][j] += av[i] * bv[j];
        }
        if (ch < 15) {
            int nb = buf ^ 1;
            As[nb][sf * 4 + 0][sr]      = pa0.x; As[nb][sf * 4 + 1][sr]      = pa0.y;
            As[nb][sf * 4 + 2][sr]      = pa0.z; As[nb][sf * 4 + 3][sr]      = pa0.w;
            As[nb][sf * 4 + 0][sr + 64] = pa1.x; As[nb][sf * 4 + 1][sr + 64] = pa1.y;
            As[nb][sf * 4 + 2][sr + 64] = pa1.z; As[nb][sf * 4 + 3][sr + 64] = pa1.w;
            Bs[nb][sf * 4 + 0][sr] = pb.x; Bs[nb][sf * 4 + 1][sr] = pb.y;
            Bs[nb][sf * 4 + 2][sr] = pb.z; Bs[nb][sf * 4 + 3][sr] = pb.w;
            __syncthreads();
            buf = nb;
        }
    }

    // epilogue: hinge + per-a reduction over this block's 64 b-columns
    int ag0 = a0 + ty * 8, bg0 = b0 + tx * 4;
    float4 qa0 = *(const float4*)&g_sq[ag0];
    float4 qa1 = *(const float4*)&g_sq[ag0 + 4];
    float4 qb  = *(const float4*)&g_sq[bg0];
    float sqav[8] = {qa0.x, qa0.y, qa0.z, qa0.w, qa1.x, qa1.y, qa1.z, qa1.w};
    float sqbv[4] = {qb.x, qb.y, qb.z, qb.w};

#pragma unroll
    for (int i = 0; i < 8; i++) {
        float rs = 0.f;
#pragma unroll
        for (int j = 0; j < 4; j++) {
            float v = sqav[i] + sqbv[j] - 2.f * acc[i][j];
            float dist = sqrtf(fmaxf(v, 1e-12f));
            float h = fmaxf(MARGIN2 - dist, 0.f);
            if (ag0 + i == bg0 + j) h = 0.f;    // exclude same class
            rs += h;
        }
        // reduce across the 16 tx lanes (contiguous within the warp half)
#pragma unroll
        for (int o = 1; o < 16; o <<= 1)
            rs += __shfl_xor_sync(0xffffffffu, rs, o, 16);
        if (tx == 0) g_anp[tb * CC + ag0 + i] = rs;   // deterministic
    }
}

// ---------------------------------------------------------------------------
// k3: final reductions -> 3 scalars
// ---------------------------------------------------------------------------
__global__ __launch_bounds__(256) void k3_final(float* __restrict__ out, int out_size) {
    int t = threadIdx.x, lane = t & 31, w = t >> 5;
    float pcs = 0.f, ans = 0.f;
#pragma unroll
    for (int e = 0; e < 4; e++) pcs += g_pc[t + e * 256];
#pragma unroll
    for (int bt = 0; bt < 16; bt++)
#pragma unroll
        for (int e = 0; e < 4; e++) ans += g_anp[bt * CC + t + e * 256];
    pcs = warpSum(pcs);
    ans = warpSum(ans);
    __shared__ float rp[8], ra[8];
    if (lane == 0) { rp[w] = pcs; ra[w] = ans; }
    __syncthreads();
    if (t == 0) {
        float P = 0.f, A = 0.f;
#pragma unroll
        for (int i = 0; i < 8; i++) { P += rp[i]; A += ra[i]; }
        float pc_mean = P * (1.f / (float)NN);
        // dist_an[a] = KK * rowsum / (NN - KK); mean over CC anchors
        float an_mean = A * ((float)KK / ((float)(NN - KK) * (float)CC));
        if (out_size > 0) out[0] = pc_mean + an_mean;
        if (out_size > 1) out[1] = pc_mean;
        if (out_size > 2) out[2] = an_mean;
    }
    for (int i = t + 3; i < out_size; i += 256) out[i] = 0.f;
}

extern "C" void kernel_launch(void* const* d_in, const int* in_sizes, int n_in,
                              void* d_out, int out_size) {
    const float* in = (const float*)d_in[0];
    // targets (d_in[1]) are arange(N)//K by construction: contiguous K-blocks.
    k1_center<<<CC, 256>>>(in);
    k2_gram<<<128, 256>>>();
    k3_final<<<1, 256>>>((float*)d_out, out_size);
}

// round 12
// speedup vs baseline: 2.3431x; 1.5278x over previous
#include <cuda_runtime.h>
#include <cuda_bf16.h>
#include <cstdint>

#define NN 8192
#define DD 256
#define KK 8
#define CC 1024
#define MARGIN2 0.7f

// persistent scratch (no allocations allowed)
__device__ __align__(16) __nv_bfloat16 g_hi[CC * DD];  // bf16 high part of centers
__device__ __align__(16) __nv_bfloat16 g_lo[CC * DD];  // bf16 low part (center - hi)
__device__ float g_sq[CC];         // ||center||^2 (exact fp32)
__device__ float g_pc[CC];         // per-class dist_pc partial sums
__device__ float g_anp[16 * CC];   // per-(b-tile, a-class) hinge partials

__device__ __forceinline__ float warpSum(float v) {
#pragma unroll
    for (int o = 16; o > 0; o >>= 1) v += __shfl_xor_sync(0xffffffffu, v, o);
    return v;
}

__device__ __forceinline__ uint32_t smem_u32(const void* p) {
    uint32_t a;
    asm("{ .reg .u64 t; cvta.to.shared.u64 t, %1; cvt.u32.u64 %0, t; }" : "=r"(a) : "l"(p));
    return a;
}

__device__ __forceinline__ void ldmx4(uint32_t& r0, uint32_t& r1, uint32_t& r2, uint32_t& r3,
                                      uint32_t addr) {
    asm volatile("ldmatrix.sync.aligned.m8n8.x4.shared.b16 {%0,%1,%2,%3}, [%4];"
                 : "=r"(r0), "=r"(r1), "=r"(r2), "=r"(r3) : "r"(addr));
}

__device__ __forceinline__ void mma16816(float* c, const uint32_t* a, uint32_t b0, uint32_t b1) {
    asm volatile("mma.sync.aligned.m16n8k16.row.col.f32.bf16.bf16.f32 "
                 "{%0,%1,%2,%3}, {%4,%5,%6,%7}, {%8,%9}, {%0,%1,%2,%3};"
                 : "+f"(c[0]), "+f"(c[1]), "+f"(c[2]), "+f"(c[3])
                 : "r"(a[0]), "r"(a[1]), "r"(a[2]), "r"(a[3]), "r"(b0), "r"(b1));
}

// ---------------------------------------------------------------------------
// k1: one block per class. Normalize 8 rows, center, ||c||^2, dist_pc,
// emit bf16 split (hi, lo) of the center.
// ---------------------------------------------------------------------------
__global__ __launch_bounds__(256) void k1_center(const float* __restrict__ in) {
    int c = blockIdx.x;
    int t = threadIdx.x;
    int w = t >> 5, lane = t & 31;

    __shared__ __align__(16) float xs[KK][DD];
    __shared__ __align__(16) float cen[DD];
    __shared__ float wred[KK];
    __shared__ float s_csq;

    const float4* row = (const float4*)(in + (size_t)(c * KK + w) * DD);
    float4 v0 = row[lane];
    float4 v1 = row[lane + 32];
    float ss = v0.x*v0.x + v0.y*v0.y + v0.z*v0.z + v0.w*v0.w
             + v1.x*v1.x + v1.y*v1.y + v1.z*v1.z + v1.w*v1.w;
    ss = warpSum(ss);
    float rn = rsqrtf(ss);
    v0.x *= rn; v0.y *= rn; v0.z *= rn; v0.w *= rn;
    v1.x *= rn; v1.y *= rn; v1.z *= rn; v1.w *= rn;
    ((float4*)xs[w])[lane] = v0;
    ((float4*)xs[w])[lane + 32] = v1;
    __syncthreads();

    float s = 0.f;
#pragma unroll
    for (int r = 0; r < KK; r++) s += xs[r][t];
    s *= (1.f / KK);
    cen[t] = s;
    __nv_bfloat16 hi = __float2bfloat16(s);
    g_hi[c * DD + t] = hi;
    g_lo[c * DD + t] = __float2bfloat16(s - __bfloat162float(hi));

    float p = warpSum(s * s);
    if (lane == 0) wred[w] = p;
    __syncthreads();
    if (t == 0) {
        float cs = 0.f;
#pragma unroll
        for (int r = 0; r < KK; r++) cs += wred[r];
        g_sq[c] = cs;
        s_csq = cs;
    }
    __syncthreads();
    float inv = rsqrtf(s_csq);

    const float4* c4 = (const float4*)cen;
    float4 c0 = c4[lane], c1 = c4[lane + 32];
    float acc = 0.f, dx;
    dx = v0.x - c0.x * inv; acc += dx * dx;
    dx = v0.y - c0.y * inv; acc += dx * dx;
    dx = v0.z - c0.z * inv; acc += dx * dx;
    dx = v0.w - c0.w * inv; acc += dx * dx;
    dx = v1.x - c1.x * inv; acc += dx * dx;
    dx = v1.y - c1.y * inv; acc += dx * dx;
    dx = v1.z - c1.z * inv; acc += dx * dx;
    dx = v1.w - c1.w * inv; acc += dx * dx;
    acc = warpSum(acc);
    if (lane == 0) wred[w] = sqrtf(acc);
    __syncthreads();
    if (t == 0) {
        float s2 = 0.f;
#pragma unroll
        for (int r = 0; r < KK; r++) s2 += wred[r];
        g_pc[c] = s2;
    }
}

// ---------------------------------------------------------------------------
// k2: bf16 Gram via mma.sync.m16n8k16 (HMMA; arch-agnostic PTX).
// Split-bf16, 3 passes: hi*hi + hi*lo + lo*hi, fp32 accumulation.
// Block tile 128a x 64b; 8 warps as 4a x 2b (warp tile 32x32); K chunks of 64.
// Smem stride 72 bf16 (144B) -> conflict-free ldmatrix. Double-buffered.
// grid = 8 * 16 = 128 blocks x 256 threads; dynamic smem 55296 B.
// ---------------------------------------------------------------------------
#define KCH 64
#define AST 72                       // smem row stride in bf16
#define ABUF_B (128 * AST * 2)       // 18432 B per A buffer
#define BBUF_B (64 * AST * 2)        // 9216 B per B buffer
#define DSMEM  (2 * ABUF_B + 2 * BBUF_B)

__global__ __launch_bounds__(256) void k2_mma() {
    extern __shared__ char dsm[];
    const int tid = threadIdx.x;
    const int lane = tid & 31, wid = tid >> 5;
    const int warp_a = wid & 3, warp_b = wid >> 2;
    const int a0 = (blockIdx.x & 7) * 128;
    const int tb = blockIdx.x >> 3;
    const int b0 = tb * 64;

    const uint32_t smbase = smem_u32(dsm);
    // buffers: A0, A1, B0, B1
    const uint32_t Aoff[2] = { 0u, ABUF_B };
    const uint32_t Boff[2] = { 2u * ABUF_B, 2u * ABUF_B + BBUF_B };

    // staging indices: A -> 4 float4/thread, B -> 2 float4/thread
    const int ar[4] = { (tid + 0) >> 3, (tid + 256) >> 3, (tid + 512) >> 3, (tid + 768) >> 3 };
    const int ac = (tid & 7) * 8;                     // bf16 col within chunk
    const int br[2] = { (tid + 0) >> 3, (tid + 256) >> 3 };

    // ldmatrix per-lane base offsets (bytes)
    const uint32_t lmRow = (uint32_t)(lane & 15);
    const uint32_t lmK   = (uint32_t)(lane >> 4) * 8; // bf16
    const uint32_t aBase0 = ((uint32_t)(warp_a * 32) + lmRow) * (AST * 2) + lmK * 2;
    const uint32_t aBase1 = aBase0 + 16 * AST * 2;
    const uint32_t bBase0 = ((uint32_t)(warp_b * 32) + lmRow) * (AST * 2) + lmK * 2;
    const uint32_t bBase1 = bBase0 + 16 * AST * 2;

    float acc[2][4][4];
#pragma unroll
    for (int i = 0; i < 2; i++)
#pragma unroll
        for (int j = 0; j < 4; j++)
#pragma unroll
            for (int q = 0; q < 4; q++) acc[i][j][q] = 0.f;

    // stage chunk 0 (pass 0: hi, kc = 0)
    {
        const __nv_bfloat16* __restrict__ S = g_hi;
        char* A = dsm + Aoff[0];
        char* B = dsm + Boff[0];
#pragma unroll
        for (int rep = 0; rep < 4; rep++)
            *(float4*)(A + (ar[rep] * AST + ac) * 2) =
                *(const float4*)&S[(size_t)(a0 + ar[rep]) * DD + ac];
#pragma unroll
        for (int rep = 0; rep < 2; rep++)
            *(float4*)(B + (br[rep] * AST + ac) * 2) =
                *(const float4*)&S[(size_t)(b0 + br[rep]) * DD + ac];
    }
    __syncthreads();

    for (int it = 0; it < 12; it++) {
        const int buf = it & 1;
        float4 pa[4], pb[2];
        if (it < 11) {
            const int nit = it + 1;
            const int pass = nit >> 2;
            const int kc = (nit & 3) * KCH;
            const __nv_bfloat16* __restrict__ Asrc = (pass == 2) ? g_lo : g_hi;
            const __nv_bfloat16* __restrict__ Bsrc = (pass == 1) ? g_lo : g_hi;
#pragma unroll
            for (int rep = 0; rep < 4; rep++)
                pa[rep] = *(const float4*)&Asrc[(size_t)(a0 + ar[rep]) * DD + kc + ac];
#pragma unroll
            for (int rep = 0; rep < 2; rep++)
                pb[rep] = *(const float4*)&Bsrc[(size_t)(b0 + br[rep]) * DD + kc + ac];
        }

        const uint32_t Abuf = smbase + Aoff[buf];
        const uint32_t Bbuf = smbase + Boff[buf];
#pragma unroll
        for (int ks = 0; ks < 4; ks++) {
            const uint32_t ko = (uint32_t)ks * 32;   // 16 bf16 = 32 B
            uint32_t af0[4], af1[4];
            ldmx4(af0[0], af0[1], af0[2], af0[3], Abuf + aBase0 + ko);
            ldmx4(af1[0], af1[1], af1[2], af1[3], Abuf + aBase1 + ko);
            uint32_t b00, b10, b01, b11, b20, b30, b21, b31;
            ldmx4(b00, b10, b01, b11, Bbuf + bBase0 + ko);  // nf0/nf1
            ldmx4(b20, b30, b21, b31, Bbuf + bBase1 + ko);  // nf2/nf3
            mma16816(acc[0][0], af0, b00, b01);
            mma16816(acc[0][1], af0, b10, b11);
            mma16816(acc[0][2], af0, b20, b21);
            mma16816(acc[0][3], af0, b30, b31);
            mma16816(acc[1][0], af1, b00, b01);
            mma16816(acc[1][1], af1, b10, b11);
            mma16816(acc[1][2], af1, b20, b21);
            mma16816(acc[1][3], af1, b30, b31);
        }

        if (it < 11) {
            const int nb = buf ^ 1;
            char* A = dsm + Aoff[nb];
            char* B = dsm + Boff[nb];
#pragma unroll
            for (int rep = 0; rep < 4; rep++)
                *(float4*)(A + (ar[rep] * AST + ac) * 2) = pa[rep];
#pragma unroll
            for (int rep = 0; rep < 2; rep++)
                *(float4*)(B + (br[rep] * AST + ac) * 2) = pb[rep];
            __syncthreads();
        }
    }
    __syncthreads();   // protect smem reuse below

    // epilogue: hinge + row sums.
    // c frag layout: c0,c1 -> m = lane/4,      n = 2*(lane%4)+{0,1}
    //               c2,c3 -> m = lane/4 + 8,  same n
    float* wsum = (float*)dsm;         // [2][128]
    const int qm = lane >> 2, qn = (lane & 3) * 2;
    float ps[2][2] = {{0.f, 0.f}, {0.f, 0.f}};
#pragma unroll
    for (int mf = 0; mf < 2; mf++) {
        const int ra = a0 + warp_a * 32 + mf * 16 + qm;
        const float sqa0 = g_sq[ra], sqa1 = g_sq[ra + 8];
#pragma unroll
        for (int nf = 0; nf < 4; nf++) {
            const int cb = b0 + warp_b * 32 + nf * 8 + qn;
            const float sqb0 = g_sq[cb], sqb1 = g_sq[cb + 1];
            const float* c = acc[mf][nf];
            float v, d, h;
            v = sqa0 + sqb0 - 2.f * c[0]; d = sqrtf(fmaxf(v, 1e-12f));
            h = fmaxf(MARGIN2 - d, 0.f); if (ra == cb) h = 0.f;           ps[mf][0] += h;
            v = sqa0 + sqb1 - 2.f * c[1]; d = sqrtf(fmaxf(v, 1e-12f));
            h = fmaxf(MARGIN2 - d, 0.f); if (ra == cb + 1) h = 0.f;       ps[mf][0] += h;
            v = sqa1 + sqb0 - 2.f * c[2]; d = sqrtf(fmaxf(v, 1e-12f));
            h = fmaxf(MARGIN2 - d, 0.f); if (ra + 8 == cb) h = 0.f;       ps[mf][1] += h;
            v = sqa1 + sqb1 - 2.f * c[3]; d = sqrtf(fmaxf(v, 1e-12f));
            h = fmaxf(MARGIN2 - d, 0.f); if (ra + 8 == cb + 1) h = 0.f;   ps[mf][1] += h;
        }
    }
#pragma unroll
    for (int mf = 0; mf < 2; mf++)
#pragma unroll
        for (int rh = 0; rh < 2; rh++) {
            float v = ps[mf][rh];
            v += __shfl_xor_sync(0xffffffffu, v, 1);
            v += __shfl_xor_sync(0xffffffffu, v, 2);
            if ((lane & 3) == 0)
                wsum[warp_b * 128 + warp_a * 32 + mf * 16 + rh * 8 + qm] = v;
        }
    __syncthreads();
    if (tid < 128)
        g_anp[tb * CC + a0 + tid] = wsum[tid] + wsum[128 + tid];   // deterministic
}

// ---------------------------------------------------------------------------
// k3: final reductions -> 3 scalars
// ---------------------------------------------------------------------------
__global__ __launch_bounds__(256) void k3_final(float* __restrict__ out, int out_size) {
    int t = threadIdx.x, lane = t & 31, w = t >> 5;
    float pcs = 0.f, ans = 0.f;
#pragma unroll
    for (int e = 0; e < 4; e++) pcs += g_pc[t + e * 256];
#pragma unroll
    for (int bt = 0; bt < 16; bt++)
#pragma unroll
        for (int e = 0; e < 4; e++) ans += g_anp[bt * CC + t + e * 256];
    pcs = warpSum(pcs);
    ans = warpSum(ans);
    __shared__ float rp[8], ra[8];
    if (lane == 0) { rp[w] = pcs; ra[w] = ans; }
    __syncthreads();
    if (t == 0) {
        float P = 0.f, A = 0.f;
#pragma unroll
        for (int i = 0; i < 8; i++) { P += rp[i]; A += ra[i]; }
        float pc_mean = P * (1.f / (float)NN);
        float an_mean = A * ((float)KK / ((float)(NN - KK) * (float)CC));
        if (out_size > 0) out[0] = pc_mean + an_mean;
        if (out_size > 1) out[1] = pc_mean;
        if (out_size > 2) out[2] = an_mean;
    }
    for (int i = t + 3; i < out_size; i += 256) out[i] = 0.f;
}

extern "C" void kernel_launch(void* const* d_in, const int* in_sizes, int n_in,
                              void* d_out, int out_size) {
    const float* in = (const float*)d_in[0];
    // targets (d_in[1]) are arange(N)//K by construction: contiguous K-blocks.
    cudaFuncSetAttribute(k2_mma, cudaFuncAttributeMaxDynamicSharedMemorySize, DSMEM);
    k1_center<<<CC, 256>>>(in);
    k2_mma<<<128, 256, DSMEM>>>();
    k3_final<<<1, 256>>>((float*)d_out, out_size);
}